// round 5
// baseline (speedup 1.0000x reference)
#include <cuda_runtime.h>
#include <cuda_bf16.h>
#include <cstdint>

// ---------------------------------------------------------------------------
// B=2, NV=8192, C=256, NP=2048, NS=32, H=4, DH=64
// ---------------------------------------------------------------------------
namespace {
constexpr int B_   = 2;
constexpr int NV_  = 8192;
constexpr int C_   = 256;
constexpr int NP2  = 2048;
constexpr int NS_  = 32;
constexpr int H_   = 4;
constexpr int DH_  = 64;
constexpr int MQ   = B_ * NV_;          // 16384
constexpr int NQT  = B_ * H_ * NV_;     // 65536 queries
constexpr int NBIN = B_ * NP2;          // 4096 bins
constexpr int SP   = 24;                // gemm smem tile pitch (bf16)
constexpr int PITCH = 260;              // attention page pitch (floats, 16B-mult)
}

// operand planes + scratch
__device__ __nv_bfloat16 g_qfh[(size_t)MQ * C_],  g_qfl[(size_t)MQ * C_];
__device__ __nv_bfloat16 g_PTh[(size_t)H_ * C_ * C_], g_PTl[(size_t)H_ * C_ * C_];
__device__ float         g_qtb[H_ * C_];
__device__ float         g_Qt [(size_t)NQT * C_];                    // fp32, 64MB
__device__ __nv_bfloat16 g_Hth[(size_t)MQ * H_ * C_], g_Htl[(size_t)MQ * H_ * C_];
__device__ __nv_bfloat16 g_vh [(size_t)MQ * C_],  g_vl [(size_t)MQ * C_];
__device__ __nv_bfloat16 g_Wvh[C_ * C_], g_Wvl[C_ * C_];
__device__ __nv_bfloat16 g_Woh[C_ * C_], g_Wol[C_ * C_];
__device__ float g_btld[C_];
__device__ int   g_cnt[NBIN];
__device__ int   g_off[NBIN + 1];
__device__ int   g_cur[NBIN];
__device__ int   g_ent[NQT];

// ---------------------------------------------------------------------------
// helpers
// ---------------------------------------------------------------------------
__device__ __forceinline__ uint32_t smem_u32(const void* p) {
    return (uint32_t)__cvta_generic_to_shared(p);
}
__device__ __forceinline__ void ldsm4(uint32_t r[4], uint32_t a) {
    asm volatile("ldmatrix.sync.aligned.m8n8.x4.shared.b16 {%0,%1,%2,%3}, [%4];\n"
                 : "=r"(r[0]), "=r"(r[1]), "=r"(r[2]), "=r"(r[3]) : "r"(a));
}
__device__ __forceinline__ void mma_bf16(float c[4], const uint32_t a[4], const uint32_t b[2]) {
    asm volatile(
        "mma.sync.aligned.m16n8k16.row.col.f32.bf16.bf16.f32 "
        "{%0,%1,%2,%3}, {%4,%5,%6,%7}, {%8,%9}, {%0,%1,%2,%3};\n"
        : "+f"(c[0]), "+f"(c[1]), "+f"(c[2]), "+f"(c[3])
        : "r"(a[0]), "r"(a[1]), "r"(a[2]), "r"(a[3]), "r"(b[0]), "r"(b[1]));
}
__device__ __forceinline__ void split1(float x, __nv_bfloat16& h, __nv_bfloat16& l) {
    h = __float2bfloat16(x);
    l = __float2bfloat16(x - __bfloat162float(h));
}
// packed f32x2 fma: d = a*b + c (two lanes)
__device__ __forceinline__ unsigned long long fma2(unsigned long long a,
                                                   unsigned long long b,
                                                   unsigned long long c) {
    unsigned long long d;
    asm("fma.rn.f32x2 %0, %1, %2, %3;" : "=l"(d) : "l"(a), "l"(b), "l"(c));
    return d;
}
__device__ __forceinline__ float2 upk(unsigned long long v) {
    return make_float2(__uint_as_float((unsigned)v),
                       __uint_as_float((unsigned)(v >> 32)));
}

// ---------------------------------------------------------------------------
// GEMM on pre-split bf16 planes (3-term bf16x3 emulation of fp32).
// out[m,n] = sum_k (Ah+Al)[m,k]*(Bh+Bl)[n,k]
// modes: 1 = fp32 out (+bias)
//        2 = bf16-plane out; blockIdx.z = head: A += z*256 cols, B += z*64
//            rows, out col offset z*64   (vhat GEMM)
//        3 = fp32 out with head remap: blockIdx.z = head z; B += z*C*C,
//            bias += z*C, out row = ((mrow>>13)*H+z)*NV + (mrow&(NV-1))
// ---------------------------------------------------------------------------
template <int NFRAG>
__global__ void __launch_bounds__(256, 1)
gemm_planes(const __nv_bfloat16* __restrict__ Ah, const __nv_bfloat16* __restrict__ Al,
            int lda,
            const __nv_bfloat16* __restrict__ Bh, const __nv_bfloat16* __restrict__ Bl,
            int ldb, int K,
            const float* __restrict__ bias,
            float* __restrict__ outf,
            __nv_bfloat16* __restrict__ oph, __nv_bfloat16* __restrict__ opl,
            int ldo, int mode)
{
    constexpr int NT = 32 * NFRAG;
    __shared__ __align__(16) __nv_bfloat16 sAh[2][128][SP];
    __shared__ __align__(16) __nv_bfloat16 sAl[2][128][SP];
    __shared__ __align__(16) __nv_bfloat16 sBh[2][NT][SP];
    __shared__ __align__(16) __nv_bfloat16 sBl[2][NT][SP];

    const int m0   = blockIdx.x * 128;
    const int n0   = blockIdx.y * NT;
    const int tid  = threadIdx.x;
    const int lane = tid & 31;
    const int wid  = tid >> 5;
    const int wm   = (wid & 1) * 64;
    const int wn   = (wid >> 1) * (8 * NFRAG);
    const int hz   = blockIdx.z;

    const __nv_bfloat16* Ahp = Ah;
    const __nv_bfloat16* Alp = Al;
    const __nv_bfloat16* Bhp = Bh;
    const __nv_bfloat16* Blp = Bl;
    const float* biasp = bias;
    int ncol_off = 0;
    if (mode == 2) {
        Ahp += hz * 256;  Alp += hz * 256;
        Bhp += (size_t)hz * 64 * ldb;  Blp += (size_t)hz * 64 * ldb;
        ncol_off = hz * 64;
    } else if (mode == 3) {
        Bhp += (size_t)hz * C_ * C_;  Blp += (size_t)hz * C_ * C_;
        biasp += hz * C_;
    }

    const int am = tid >> 1;
    const int ak = (tid & 1) << 3;
    const int bn = tid >> 1;
    const int bk = (tid & 1) << 3;
    const bool bact = (NFRAG == 4) || (tid < 2 * NT);

    const int lrow = (lane & 7) + (lane & 8);
    const int lcol = (lane & 16) ? 8 : 0;
    const int fn = lane >> 2;
    const int fc = (lane & 3) * 2;

    float acc[4][NFRAG][4];
#pragma unroll
    for (int i = 0; i < 4; i++)
#pragma unroll
        for (int j = 0; j < NFRAG; j++)
#pragma unroll
            for (int r = 0; r < 4; r++) acc[i][j][r] = 0.f;

    uint4 rah, ral, rbh, rbl;
    auto ldg_chunk = [&](int kc) {
        const int k0 = kc * 16;
        rah = *(const uint4*)&Ahp[(size_t)(m0 + am) * lda + k0 + ak];
        ral = *(const uint4*)&Alp[(size_t)(m0 + am) * lda + k0 + ak];
        if (bact) {
            rbh = *(const uint4*)&Bhp[(size_t)(n0 + bn) * ldb + k0 + bk];
            rbl = *(const uint4*)&Blp[(size_t)(n0 + bn) * ldb + k0 + bk];
        }
    };
    auto st_chunk = [&](int buf) {
        *(uint4*)&sAh[buf][am][ak] = rah;
        *(uint4*)&sAl[buf][am][ak] = ral;
        if (bact) {
            *(uint4*)&sBh[buf][bn][bk] = rbh;
            *(uint4*)&sBl[buf][bn][bk] = rbl;
        }
    };
    auto compute = [&](int buf) {
        uint32_t Ahf[4][4], Alf[4][4], Bhf[NFRAG][2], Blf[NFRAG][2];
#pragma unroll
        for (int mf = 0; mf < 4; mf++) {
            const int mr = wm + mf * 16 + lrow;
            ldsm4(Ahf[mf], smem_u32(&sAh[buf][mr][lcol]));
            ldsm4(Alf[mf], smem_u32(&sAl[buf][mr][lcol]));
        }
#pragma unroll
        for (int nf = 0; nf < NFRAG; nf++) {
            const int n = wn + nf * 8 + fn;
            Bhf[nf][0] = *(const uint32_t*)&sBh[buf][n][fc];
            Bhf[nf][1] = *(const uint32_t*)&sBh[buf][n][fc + 8];
            Blf[nf][0] = *(const uint32_t*)&sBl[buf][n][fc];
            Blf[nf][1] = *(const uint32_t*)&sBl[buf][n][fc + 8];
        }
#pragma unroll
        for (int mf = 0; mf < 4; mf++)
#pragma unroll
            for (int nf = 0; nf < NFRAG; nf++) {
                mma_bf16(acc[mf][nf], Ahf[mf], Bhf[nf]);
                mma_bf16(acc[mf][nf], Ahf[mf], Blf[nf]);
                mma_bf16(acc[mf][nf], Alf[mf], Bhf[nf]);
            }
    };

    const int NKC = K / 16;
    ldg_chunk(0);
    st_chunk(0);
    __syncthreads();
    for (int kc = 0; kc < NKC; kc++) {
        const int buf = kc & 1;
        if (kc + 1 < NKC) ldg_chunk(kc + 1);
        compute(buf);
        if (kc + 1 < NKC) {
            st_chunk(buf ^ 1);
            __syncthreads();
        }
    }

#pragma unroll
    for (int mf = 0; mf < 4; mf++)
#pragma unroll
        for (int nf = 0; nf < NFRAG; nf++) {
            const int ncol = n0 + wn + nf * 8 + fc;
            const float bx = biasp ? biasp[ncol]     : 0.f;
            const float by = biasp ? biasp[ncol + 1] : 0.f;
#pragma unroll
            for (int half = 0; half < 2; half++) {
                const int mrow = m0 + wm + mf * 16 + (lane >> 2) + half * 8;
                const float ox = acc[mf][nf][half * 2]     + bx;
                const float oy = acc[mf][nf][half * 2 + 1] + by;
                if (mode == 1) {
                    float2 o; o.x = ox; o.y = oy;
                    *(float2*)&outf[(size_t)mrow * ldo + ncol] = o;
                } else if (mode == 2) {
                    const size_t idx = (size_t)mrow * ldo + ncol_off + ncol;
                    __nv_bfloat162 h2, l2;
                    split1(ox, h2.x, l2.x);
                    split1(oy, h2.y, l2.y);
                    *(__nv_bfloat162*)&oph[idx] = h2;
                    *(__nv_bfloat162*)&opl[idx] = l2;
                } else {  // mode 3
                    const size_t orow = ((size_t)((mrow >> 13) * H_ + hz)) * NV_
                                        + (mrow & (NV_ - 1));
                    float2 o; o.x = ox; o.y = oy;
                    *(float2*)&outf[orow * ldo + ncol] = o;
                }
            }
        }
}

// ---------------------------------------------------------------------------
// Precompute
// ---------------------------------------------------------------------------
__global__ void split_weights(const float* __restrict__ Wv,
                              const float* __restrict__ Wo) {
    const int r = blockIdx.x;     // 256
    const int c = threadIdx.x;    // 256
    const int i = r * C_ + c;
    split1(Wv[i], g_Wvh[i], g_Wvl[i]);
    split1(Wo[i], g_Woh[i], g_Wol[i]);
    if (i < NBIN) g_cnt[i] = 0;
}

// PT[h][j][c] = sum_d Wq[h*64+d][c] * Wk[h*64+d][j];  qtb[h][j] = bq.Wk col j
__global__ void pcomp_kernel(const float* __restrict__ Wq,
                             const float* __restrict__ Wk,
                             const float* __restrict__ bq) {
    const int hj = blockIdx.x;      // 1024
    const int h  = hj >> 8;
    const int j  = hj & 255;
    const int c  = threadIdx.x;     // 256
    float s = 0.f;
#pragma unroll 16
    for (int d = 0; d < 64; d++)
        s = fmaf(Wq[(h * 64 + d) * C_ + c], Wk[(h * 64 + d) * C_ + j], s);
    split1(s, g_PTh[(size_t)hj * C_ + c], g_PTl[(size_t)hj * C_ + c]);
    if (c == 0) {
        float t = 0.f;
        for (int d = 0; d < 64; d++)
            t = fmaf(bq[h * 64 + d], Wk[(h * 64 + d) * C_ + j], t);
        g_qtb[hj] = t;
    }
}

__global__ void split_qfeat(const float* __restrict__ qf) {
    const int t = blockIdx.x * 256 + threadIdx.x;   // 1M float4
    const float4 v = ((const float4*)qf)[t];
    __nv_bfloat16 h[4], l[4];
    split1(v.x, h[0], l[0]); split1(v.y, h[1], l[1]);
    split1(v.z, h[2], l[2]); split1(v.w, h[3], l[3]);
    *(uint2*)&g_qfh[(size_t)t * 4] = *(const uint2*)h;
    *(uint2*)&g_qfl[(size_t)t * 4] = *(const uint2*)l;
}

__global__ void btld_kernel(const float* __restrict__ Wo,
                            const float* __restrict__ bv,
                            const float* __restrict__ bo) {
    const int i = threadIdx.x;   // 256
    float s = bo[i];
    for (int j = 0; j < C_; j++) s = fmaf(Wo[(size_t)i * C_ + j], bv[j], s);
    g_btld[i] = s;
}

// ---------------------------------------------------------------------------
// Bucketing
// ---------------------------------------------------------------------------
__global__ void hist_kernel(const int* __restrict__ nidx) {
    const int t = blockIdx.x * 256 + threadIdx.x;
    const int b = t >> 15;
    atomicAdd(&g_cnt[(b << 11) | nidx[t]], 1);
}

__global__ void scan_kernel() {
    __shared__ int tsum[1024];
    const int t = threadIdx.x;
    const int4 v = ((const int4*)g_cnt)[t];
    const int s0 = v.x, s01 = v.x + v.y, s012 = s01 + v.z;
    const int tot = s012 + v.w;
    tsum[t] = tot;
    __syncthreads();
    for (int off = 1; off < 1024; off <<= 1) {
        int x = (t >= off) ? tsum[t - off] : 0;
        __syncthreads();
        tsum[t] += x;
        __syncthreads();
    }
    const int base = tsum[t] - tot;
    g_off[4 * t]     = base;          g_cur[4 * t]     = base;
    g_off[4 * t + 1] = base + s0;     g_cur[4 * t + 1] = base + s0;
    g_off[4 * t + 2] = base + s01;    g_cur[4 * t + 2] = base + s01;
    g_off[4 * t + 3] = base + s012;   g_cur[4 * t + 3] = base + s012;
    if (t == 1023) g_off[NBIN] = tsum[1023];
}

__global__ void scatter_kernel(const int* __restrict__ nidx) {
    const int t = blockIdx.x * 256 + threadIdx.x;
    const int b  = t >> 15;
    const int h  = (t >> 13) & 3;
    const int nv = t & (NV_ - 1);
    const int pos = atomicAdd(&g_cur[(b << 11) | nidx[t]], 1);
    g_ent[pos] = (h << 16) | nv;
}

// ---------------------------------------------------------------------------
// Bucketed attention, s-major pages + packed f32x2 math.
// smem: ssum[32][PITCH] (gf+kp), sgf[32][PITCH] (gf), sq[8][256] (query rows)
// ---------------------------------------------------------------------------
__global__ void __launch_bounds__(256)
attn_pages(const float* __restrict__ gf, const float* __restrict__ kp)
{
    extern __shared__ float sm[];
    float* ssum = sm;                       // [32][PITCH]
    float* sgf  = sm + 32 * PITCH;          // [32][PITCH]
    float* sq   = sm + 64 * PITCH;          // [8][256]

    const int bin  = blockIdx.x;
    const int b    = bin >> 11;
    const int page = bin & (NP2 - 1);
    const int off  = g_off[bin];
    const int cnt  = g_off[bin + 1] - off;
    if (cnt == 0) return;

    const int tid  = threadIdx.x;
    const int lane = tid & 31;
    const int w    = tid >> 5;

    const float* gfb = gf + (size_t)b * C_ * (NP2 * NS_) + page * NS_;
    const float* kpb = kp + (size_t)b * C_ * (NP2 * NS_) + page * NS_;

    // load + transpose to s-major
#pragma unroll
    for (int it = 0; it < 8; it++) {
        const int i = it * 256 + tid;       // 2048 float4 slots
        const int c = i >> 3;
        const int j = (i & 7) * 4;
        const float4 g = *(const float4*)(gfb + (size_t)c * (NP2 * NS_) + j);
        const float4 k = *(const float4*)(kpb + (size_t)c * (NP2 * NS_) + j);
        const float gr[4] = {g.x, g.y, g.z, g.w};
        const float kr[4] = {k.x, k.y, k.z, k.w};
#pragma unroll
        for (int r = 0; r < 4; r++) {
            sgf [(j + r) * PITCH + c] = gr[r];
            ssum[(j + r) * PITCH + c] = gr[r] + kr[r];
        }
    }
    __syncthreads();

    float* qw = sq + w * 256;
    const float* krow = ssum + lane * PITCH;

    for (int e = w; e < cnt; e += 8) {
        const int ent = g_ent[off + e];
        const int h   = ent >> 16;
        const int nv  = ent & 0xffff;
        const size_t qrow = ((size_t)(b * H_ + h)) * NV_ + nv;

        // stage query row (coalesced 1KB read)
        *(float4*)&qw[lane * 8]     = *(const float4*)&g_Qt[qrow * C_ + lane * 8];
        *(float4*)&qw[lane * 8 + 4] = *(const float4*)&g_Qt[qrow * C_ + lane * 8 + 4];
        __syncwarp();

        // score for s = lane : packed f32x2 dot over 256 channels
        unsigned long long a0 = 0, a1 = 0, a2 = 0, a3 = 0;
#pragma unroll 8
        for (int c = 0; c < 256; c += 8) {
            const ulonglong2 q01 = *(const ulonglong2*)&qw[c];
            const ulonglong2 q23 = *(const ulonglong2*)&qw[c + 4];
            const ulonglong2 k01 = *(const ulonglong2*)&krow[c];
            const ulonglong2 k23 = *(const ulonglong2*)&krow[c + 4];
            a0 = fma2(q01.x, k01.x, a0);
            a1 = fma2(q01.y, k01.y, a1);
            a2 = fma2(q23.x, k23.x, a2);
            a3 = fma2(q23.y, k23.y, a3);
        }
        const float2 f0 = upk(a0), f1 = upk(a1), f2 = upk(a2), f3 = upk(a3);
        float sc = ((f0.x + f0.y) + (f1.x + f1.y)) + ((f2.x + f2.y) + (f3.x + f3.y));
        sc *= 0.125f;

        // softmax over 32 lanes
        float mx = sc;
#pragma unroll
        for (int o = 16; o; o >>= 1) mx = fmaxf(mx, __shfl_xor_sync(0xffffffffu, mx, o));
        const float ex = __expf(sc - mx);
        float sum = ex;
#pragma unroll
        for (int o = 16; o; o >>= 1) sum += __shfl_xor_sync(0xffffffffu, sum, o);
        const float pr = ex / sum;

        // ghat: lane owns c = lane*4..+3 and 128+lane*4..+3
        unsigned long long b0 = 0, b1 = 0, b2 = 0, b3 = 0;
#pragma unroll 8
        for (int s = 0; s < 32; s++) {
            const float ps = __shfl_sync(0xffffffffu, pr, s);
            unsigned long long pp;
            asm("mov.b64 %0, {%1,%1};" : "=l"(pp) : "r"(__float_as_uint(ps)));
            const ulonglong2 ga = *(const ulonglong2*)&sgf[s * PITCH + lane * 4];
            const ulonglong2 gb = *(const ulonglong2*)&sgf[s * PITCH + 128 + lane * 4];
            b0 = fma2(pp, ga.x, b0);
            b1 = fma2(pp, ga.y, b1);
            b2 = fma2(pp, gb.x, b2);
            b3 = fma2(pp, gb.y, b3);
        }

        const size_t obase = (((size_t)(b * NV_ + nv)) * H_ + h) * C_;
        const float2 g0 = upk(b0), g1 = upk(b1), g2 = upk(b2), g3 = upk(b3);
        __nv_bfloat162 h01, l01, h23, l23;
        split1(g0.x, h01.x, l01.x); split1(g0.y, h01.y, l01.y);
        split1(g1.x, h23.x, l23.x); split1(g1.y, h23.y, l23.y);
        uint2 uh, ul;
        uh.x = *(const unsigned*)&h01; uh.y = *(const unsigned*)&h23;
        ul.x = *(const unsigned*)&l01; ul.y = *(const unsigned*)&l23;
        *(uint2*)&g_Hth[obase + lane * 4] = uh;
        *(uint2*)&g_Htl[obase + lane * 4] = ul;
        split1(g2.x, h01.x, l01.x); split1(g2.y, h01.y, l01.y);
        split1(g3.x, h23.x, l23.x); split1(g3.y, h23.y, l23.y);
        uh.x = *(const unsigned*)&h01; uh.y = *(const unsigned*)&h23;
        ul.x = *(const unsigned*)&l01; ul.y = *(const unsigned*)&l23;
        *(uint2*)&g_Hth[obase + 128 + lane * 4] = uh;
        *(uint2*)&g_Htl[obase + 128 + lane * 4] = ul;
    }
}

// ---------------------------------------------------------------------------
// Launch
// ---------------------------------------------------------------------------
extern "C" void kernel_launch(void* const* d_in, const int* in_sizes, int n_in,
                              void* d_out, int out_size)
{
    const float* q_feat     = (const float*)d_in[0];
    const float* group_feat = (const float*)d_in[1];
    const float* k_pos      = (const float*)d_in[2];
    const int*   nidx       = (const int*)  d_in[3];
    const float* Wq = (const float*)d_in[4];  const float* bq = (const float*)d_in[5];
    const float* Wk = (const float*)d_in[6];
    const float* Wv = (const float*)d_in[8];  const float* bv = (const float*)d_in[9];
    const float* Wo = (const float*)d_in[10]; const float* bo = (const float*)d_in[11];
    float* out = (float*)d_out;

    __nv_bfloat16 *qfh, *qfl, *PTh, *PTl, *Hth, *Htl, *vh, *vl;
    __nv_bfloat16 *Wvh, *Wvl, *Woh, *Wol;
    float *Qt, *btld, *qtb;
    cudaGetSymbolAddress((void**)&qfh, g_qfh);   cudaGetSymbolAddress((void**)&qfl, g_qfl);
    cudaGetSymbolAddress((void**)&PTh, g_PTh);   cudaGetSymbolAddress((void**)&PTl, g_PTl);
    cudaGetSymbolAddress((void**)&Hth, g_Hth);   cudaGetSymbolAddress((void**)&Htl, g_Htl);
    cudaGetSymbolAddress((void**)&vh,  g_vh);    cudaGetSymbolAddress((void**)&vl,  g_vl);
    cudaGetSymbolAddress((void**)&Wvh, g_Wvh);   cudaGetSymbolAddress((void**)&Wvl, g_Wvl);
    cudaGetSymbolAddress((void**)&Woh, g_Woh);   cudaGetSymbolAddress((void**)&Wol, g_Wol);
    cudaGetSymbolAddress((void**)&Qt,  g_Qt);
    cudaGetSymbolAddress((void**)&btld, g_btld);
    cudaGetSymbolAddress((void**)&qtb,  g_qtb);

    const int attn_smem = (64 * PITCH + 8 * 256) * (int)sizeof(float);  // 74752
    cudaFuncSetAttribute(attn_pages, cudaFuncAttributeMaxDynamicSharedMemorySize,
                         attn_smem);

    // precompute + bucketing
    split_weights<<<256, 256>>>(Wv, Wo);
    pcomp_kernel<<<1024, 256>>>(Wq, Wk, bq);
    split_qfeat<<<(MQ * C_ / 4) / 256, 256>>>(q_feat);
    btld_kernel<<<1, 256>>>(Wo, bv, bo);
    hist_kernel<<<NQT / 256, 256>>>(nidx);
    scan_kernel<<<1, 1024>>>();
    scatter_kernel<<<NQT / 256, 256>>>(nidx);

    // Q-tilde composite: qfeat @ PT_h + qtb_h -> g_Qt [B,H,NV,256]  (mode 3)
    gemm_planes<4><<<dim3(MQ / 128, 2, H_), 256>>>(
        qfh, qfl, C_, PTh, PTl, C_, C_, qtb, Qt, nullptr, nullptr, C_, 3);
    // bucketed attention -> g_Hat planes [B,NV,H,256]
    attn_pages<<<NBIN, 256, attn_smem>>>(group_feat, k_pos);
    // vhat: per-head ghat_h @ Wv_h^T -> v planes [MQ,256]           (mode 2)
    gemm_planes<2><<<dim3(MQ / 128, 1, H_), 256>>>(
        Hth, Htl, H_ * C_, Wvh, Wvl, C_, C_, nullptr, nullptr, vh, vl, C_, 2);
    // out: v @ Wo^T + btld -> d_out fp32                            (mode 1)
    gemm_planes<4><<<dim3(MQ / 128, 2), 256>>>(
        vh, vl, C_, Woh, Wol, C_, C_, btld, out, nullptr, nullptr, C_, 1);
}

// round 6
// speedup vs baseline: 1.1586x; 1.1586x over previous
#include <cuda_runtime.h>
#include <cuda_bf16.h>
#include <cstdint>

// ---------------------------------------------------------------------------
// B=2, NV=8192, C=256, NP=2048, NS=32, H=4, DH=64
// ---------------------------------------------------------------------------
namespace {
constexpr int B_   = 2;
constexpr int NV_  = 8192;
constexpr int C_   = 256;
constexpr int NP2  = 2048;
constexpr int NS_  = 32;
constexpr int H_   = 4;
constexpr int DH_  = 64;
constexpr int MQ   = B_ * NV_;          // 16384
constexpr int NQT  = B_ * H_ * NV_;     // 65536 queries
constexpr int NBIN = B_ * NP2;          // 4096 bins
constexpr int SP   = 24;                // gemm smem tile pitch (bf16)
constexpr int PITCH = 260;              // attention page pitch (floats)
}

// operand planes + scratch
__device__ __nv_bfloat16 g_qfh[(size_t)MQ * C_],  g_qfl[(size_t)MQ * C_];
__device__ __nv_bfloat16 g_Qh [(size_t)NQT * DH_], g_Ql [(size_t)NQT * DH_];
__device__ float         g_Qt [(size_t)NQT * C_];                    // fp32, 64MB
__device__ __nv_bfloat16 g_Hth[(size_t)MQ * H_ * C_], g_Htl[(size_t)MQ * H_ * C_];
__device__ __nv_bfloat16 g_vh [(size_t)MQ * C_],  g_vl [(size_t)MQ * C_];
__device__ __nv_bfloat16 g_Wqh[C_ * C_], g_Wql[C_ * C_];
__device__ __nv_bfloat16 g_WkTh[C_ * C_], g_WkTl[C_ * C_];
__device__ __nv_bfloat16 g_Wvh[C_ * C_], g_Wvl[C_ * C_];
__device__ __nv_bfloat16 g_Woh[C_ * C_], g_Wol[C_ * C_];
__device__ float g_btld[C_];
__device__ int   g_cnt[NBIN];
__device__ int   g_off[NBIN + 1];
__device__ int   g_cur[NBIN];
__device__ int   g_ent[NQT];

// ---------------------------------------------------------------------------
// helpers
// ---------------------------------------------------------------------------
__device__ __forceinline__ uint32_t smem_u32(const void* p) {
    return (uint32_t)__cvta_generic_to_shared(p);
}
__device__ __forceinline__ void ldsm4(uint32_t r[4], uint32_t a) {
    asm volatile("ldmatrix.sync.aligned.m8n8.x4.shared.b16 {%0,%1,%2,%3}, [%4];\n"
                 : "=r"(r[0]), "=r"(r[1]), "=r"(r[2]), "=r"(r[3]) : "r"(a));
}
__device__ __forceinline__ void mma_bf16(float c[4], const uint32_t a[4], const uint32_t b[2]) {
    asm volatile(
        "mma.sync.aligned.m16n8k16.row.col.f32.bf16.bf16.f32 "
        "{%0,%1,%2,%3}, {%4,%5,%6,%7}, {%8,%9}, {%0,%1,%2,%3};\n"
        : "+f"(c[0]), "+f"(c[1]), "+f"(c[2]), "+f"(c[3])
        : "r"(a[0]), "r"(a[1]), "r"(a[2]), "r"(a[3]), "r"(b[0]), "r"(b[1]));
}
__device__ __forceinline__ void split1(float x, __nv_bfloat16& h, __nv_bfloat16& l) {
    h = __float2bfloat16(x);
    l = __float2bfloat16(x - __bfloat162float(h));
}
__device__ __forceinline__ unsigned long long fma2(unsigned long long a,
                                                   unsigned long long b,
                                                   unsigned long long c) {
    unsigned long long d;
    asm("fma.rn.f32x2 %0, %1, %2, %3;" : "=l"(d) : "l"(a), "l"(b), "l"(c));
    return d;
}
__device__ __forceinline__ float2 upk(unsigned long long v) {
    return make_float2(__uint_as_float((unsigned)v),
                       __uint_as_float((unsigned)(v >> 32)));
}

// ---------------------------------------------------------------------------
// GEMM on pre-split bf16 planes (3-term bf16x3 emulation of fp32).
// out[m,n] = sum_k (Ah+Al)[m,k]*(Bh+Bl)[n,k]
// mode 0: Q-projection epilogue -> bf16 planes in [B,H,NV,64] layout
// mode 1: fp32 out (+bias)
// mode 2: bf16-plane out; blockIdx.z = head (vhat GEMM): A += z*256 cols,
//         B += z*64 rows, out col offset z*64
// qtsel: B k-offset = ((m0>>13)&3)*64  (per-head Wk^T slice, Qt GEMM)
// ---------------------------------------------------------------------------
template <int NFRAG>
__global__ void __launch_bounds__(256, 1)
gemm_planes(const __nv_bfloat16* __restrict__ Ah, const __nv_bfloat16* __restrict__ Al,
            int lda,
            const __nv_bfloat16* __restrict__ Bh, const __nv_bfloat16* __restrict__ Bl,
            int ldb, int K,
            const float* __restrict__ bias,
            float* __restrict__ outf,
            __nv_bfloat16* __restrict__ oph, __nv_bfloat16* __restrict__ opl,
            int ldo, int mode, int qtsel)
{
    constexpr int NT = 32 * NFRAG;
    __shared__ __align__(16) __nv_bfloat16 sAh[2][128][SP];
    __shared__ __align__(16) __nv_bfloat16 sAl[2][128][SP];
    __shared__ __align__(16) __nv_bfloat16 sBh[2][NT][SP];
    __shared__ __align__(16) __nv_bfloat16 sBl[2][NT][SP];

    const int m0   = blockIdx.x * 128;
    const int n0   = blockIdx.y * NT;
    const int tid  = threadIdx.x;
    const int lane = tid & 31;
    const int wid  = tid >> 5;
    const int wm   = (wid & 1) * 64;
    const int wn   = (wid >> 1) * (8 * NFRAG);

    const int koff = qtsel ? ((m0 >> 13) & 3) * 64 : 0;
    const __nv_bfloat16* Ahp = Ah;
    const __nv_bfloat16* Alp = Al;
    const __nv_bfloat16* Bhp = Bh;
    const __nv_bfloat16* Blp = Bl;
    int ncol_off = 0;
    if (mode == 2) {
        const int hz = blockIdx.z;
        Ahp += hz * 256;  Alp += hz * 256;
        Bhp += (size_t)hz * 64 * ldb;  Blp += (size_t)hz * 64 * ldb;
        ncol_off = hz * 64;
    }

    const int am = tid >> 1;
    const int ak = (tid & 1) << 3;
    const int bn = tid >> 1;
    const int bk = (tid & 1) << 3;
    const bool bact = (NFRAG == 4) || (tid < 2 * NT);

    const int lrow = (lane & 7) + (lane & 8);
    const int lcol = (lane & 16) ? 8 : 0;
    const int fn = lane >> 2;
    const int fc = (lane & 3) * 2;

    float acc[4][NFRAG][4];
#pragma unroll
    for (int i = 0; i < 4; i++)
#pragma unroll
        for (int j = 0; j < NFRAG; j++)
#pragma unroll
            for (int r = 0; r < 4; r++) acc[i][j][r] = 0.f;

    uint4 rah, ral, rbh, rbl;
    auto ldg_chunk = [&](int kc) {
        const int k0 = kc * 16;
        rah = *(const uint4*)&Ahp[(size_t)(m0 + am) * lda + k0 + ak];
        ral = *(const uint4*)&Alp[(size_t)(m0 + am) * lda + k0 + ak];
        if (bact) {
            rbh = *(const uint4*)&Bhp[(size_t)(n0 + bn) * ldb + koff + k0 + bk];
            rbl = *(const uint4*)&Blp[(size_t)(n0 + bn) * ldb + koff + k0 + bk];
        }
    };
    auto st_chunk = [&](int buf) {
        *(uint4*)&sAh[buf][am][ak] = rah;
        *(uint4*)&sAl[buf][am][ak] = ral;
        if (bact) {
            *(uint4*)&sBh[buf][bn][bk] = rbh;
            *(uint4*)&sBl[buf][bn][bk] = rbl;
        }
    };
    auto compute = [&](int buf) {
        uint32_t Ahf[4][4], Alf[4][4], Bhf[NFRAG][2], Blf[NFRAG][2];
#pragma unroll
        for (int mf = 0; mf < 4; mf++) {
            const int mr = wm + mf * 16 + lrow;
            ldsm4(Ahf[mf], smem_u32(&sAh[buf][mr][lcol]));
            ldsm4(Alf[mf], smem_u32(&sAl[buf][mr][lcol]));
        }
#pragma unroll
        for (int nf = 0; nf < NFRAG; nf++) {
            const int n = wn + nf * 8 + fn;
            Bhf[nf][0] = *(const uint32_t*)&sBh[buf][n][fc];
            Bhf[nf][1] = *(const uint32_t*)&sBh[buf][n][fc + 8];
            Blf[nf][0] = *(const uint32_t*)&sBl[buf][n][fc];
            Blf[nf][1] = *(const uint32_t*)&sBl[buf][n][fc + 8];
        }
#pragma unroll
        for (int mf = 0; mf < 4; mf++)
#pragma unroll
            for (int nf = 0; nf < NFRAG; nf++) {
                mma_bf16(acc[mf][nf], Ahf[mf], Bhf[nf]);
                mma_bf16(acc[mf][nf], Ahf[mf], Blf[nf]);
                mma_bf16(acc[mf][nf], Alf[mf], Bhf[nf]);
            }
    };

    const int NKC = K / 16;
    ldg_chunk(0);
    st_chunk(0);
    __syncthreads();
    for (int kc = 0; kc < NKC; kc++) {
        const int buf = kc & 1;
        if (kc + 1 < NKC) ldg_chunk(kc + 1);
        compute(buf);
        if (kc + 1 < NKC) {
            st_chunk(buf ^ 1);
            __syncthreads();
        }
    }

#pragma unroll
    for (int mf = 0; mf < 4; mf++)
#pragma unroll
        for (int nf = 0; nf < NFRAG; nf++) {
            const int ncol = n0 + wn + nf * 8 + fc;
            const float bx = bias ? bias[ncol]     : 0.f;
            const float by = bias ? bias[ncol + 1] : 0.f;
#pragma unroll
            for (int half = 0; half < 2; half++) {
                const int mrow = m0 + wm + mf * 16 + (lane >> 2) + half * 8;
                const float ox = acc[mf][nf][half * 2]     + bx;
                const float oy = acc[mf][nf][half * 2 + 1] + by;
                if (mode == 0) {
                    const int bb = mrow >> 13;
                    const int nv = mrow & (NV_ - 1);
                    const int hh = ncol >> 6;
                    const int d  = ncol & 63;
                    const size_t idx = (((size_t)(bb * H_ + hh)) * NV_ + nv) * DH_ + d;
                    __nv_bfloat162 h2, l2;
                    split1(ox, h2.x, l2.x);
                    split1(oy, h2.y, l2.y);
                    *(__nv_bfloat162*)&oph[idx] = h2;
                    *(__nv_bfloat162*)&opl[idx] = l2;
                } else if (mode == 1) {
                    float2 o; o.x = ox; o.y = oy;
                    *(float2*)&outf[(size_t)mrow * ldo + ncol] = o;
                } else {
                    const size_t idx = (size_t)mrow * ldo + ncol_off + ncol;
                    __nv_bfloat162 h2, l2;
                    split1(ox, h2.x, l2.x);
                    split1(oy, h2.y, l2.y);
                    *(__nv_bfloat162*)&oph[idx] = h2;
                    *(__nv_bfloat162*)&opl[idx] = l2;
                }
            }
        }
}

// ---------------------------------------------------------------------------
// Precompute
// ---------------------------------------------------------------------------
__global__ void split_weights(const float* __restrict__ Wq,
                              const float* __restrict__ Wk,
                              const float* __restrict__ Wv,
                              const float* __restrict__ Wo) {
    const int r = blockIdx.x;     // 256
    const int c = threadIdx.x;    // 256
    const int i = r * C_ + c;
    split1(Wq[i], g_Wqh[i], g_Wql[i]);
    split1(Wk[c * C_ + r], g_WkTh[i], g_WkTl[i]);   // WkT[r][c] = Wk[c][r]
    split1(Wv[i], g_Wvh[i], g_Wvl[i]);
    split1(Wo[i], g_Woh[i], g_Wol[i]);
    if (i < NBIN) g_cnt[i] = 0;
}

__global__ void split_qfeat(const float* __restrict__ qf) {
    const int t = blockIdx.x * 256 + threadIdx.x;   // 1M float4
    const float4 v = ((const float4*)qf)[t];
    __nv_bfloat16 h[4], l[4];
    split1(v.x, h[0], l[0]); split1(v.y, h[1], l[1]);
    split1(v.z, h[2], l[2]); split1(v.w, h[3], l[3]);
    *(uint2*)&g_qfh[(size_t)t * 4] = *(const uint2*)h;
    *(uint2*)&g_qfl[(size_t)t * 4] = *(const uint2*)l;
}

// parallel btld: one block per output channel, tree reduction
__global__ void btld_kernel(const float* __restrict__ Wo,
                            const float* __restrict__ bv,
                            const float* __restrict__ bo) {
    __shared__ float red[256];
    const int i = blockIdx.x;
    const int t = threadIdx.x;
    red[t] = Wo[(size_t)i * C_ + t] * bv[t];
    __syncthreads();
#pragma unroll
    for (int o = 128; o; o >>= 1) {
        if (t < o) red[t] += red[t + o];
        __syncthreads();
    }
    if (t == 0) g_btld[i] = red[0] + bo[i];
}

// ---------------------------------------------------------------------------
// Bucketing
// ---------------------------------------------------------------------------
__global__ void hist_kernel(const int* __restrict__ nidx) {
    const int t = blockIdx.x * 256 + threadIdx.x;
    const int b = t >> 15;
    atomicAdd(&g_cnt[(b << 11) | nidx[t]], 1);
}

__global__ void scan_kernel() {
    __shared__ int tsum[1024];
    const int t = threadIdx.x;
    const int4 v = ((const int4*)g_cnt)[t];
    const int s0 = v.x, s01 = v.x + v.y, s012 = s01 + v.z;
    const int tot = s012 + v.w;
    tsum[t] = tot;
    __syncthreads();
    for (int off = 1; off < 1024; off <<= 1) {
        int x = (t >= off) ? tsum[t - off] : 0;
        __syncthreads();
        tsum[t] += x;
        __syncthreads();
    }
    const int base = tsum[t] - tot;
    g_off[4 * t]     = base;          g_cur[4 * t]     = base;
    g_off[4 * t + 1] = base + s0;     g_cur[4 * t + 1] = base + s0;
    g_off[4 * t + 2] = base + s01;    g_cur[4 * t + 2] = base + s01;
    g_off[4 * t + 3] = base + s012;   g_cur[4 * t + 3] = base + s012;
    if (t == 1023) g_off[NBIN] = tsum[1023];
}

__global__ void scatter_kernel(const int* __restrict__ nidx) {
    const int t = blockIdx.x * 256 + threadIdx.x;
    const int b  = t >> 15;
    const int h  = (t >> 13) & 3;
    const int nv = t & (NV_ - 1);
    const int pos = atomicAdd(&g_cur[(b << 11) | nidx[t]], 1);
    g_ent[pos] = (h << 16) | nv;
}

// ---------------------------------------------------------------------------
// Bucketed attention, s-major pages + packed f32x2 math.
// ---------------------------------------------------------------------------
__global__ void __launch_bounds__(256)
attn_pages(const float* __restrict__ gf, const float* __restrict__ kp)
{
    extern __shared__ float sm[];
    float* ssum = sm;                       // [32][PITCH]
    float* sgf  = sm + 32 * PITCH;          // [32][PITCH]
    float* sq   = sm + 64 * PITCH;          // [8][256]

    const int bin  = blockIdx.x;
    const int b    = bin >> 11;
    const int page = bin & (NP2 - 1);
    const int off  = g_off[bin];
    const int cnt  = g_off[bin + 1] - off;
    if (cnt == 0) return;

    const int tid  = threadIdx.x;
    const int lane = tid & 31;
    const int w    = tid >> 5;

    const float* gfb = gf + (size_t)b * C_ * (NP2 * NS_) + page * NS_;
    const float* kpb = kp + (size_t)b * C_ * (NP2 * NS_) + page * NS_;

#pragma unroll
    for (int it = 0; it < 8; it++) {
        const int i = it * 256 + tid;       // 2048 float4 slots
        const int c = i >> 3;
        const int j = (i & 7) * 4;
        const float4 g = *(const float4*)(gfb + (size_t)c * (NP2 * NS_) + j);
        const float4 k = *(const float4*)(kpb + (size_t)c * (NP2 * NS_) + j);
        const float gr[4] = {g.x, g.y, g.z, g.w};
        const float kr[4] = {k.x, k.y, k.z, k.w};
#pragma unroll
        for (int r = 0; r < 4; r++) {
            sgf [(j + r) * PITCH + c] = gr[r];
            ssum[(j + r) * PITCH + c] = gr[r] + kr[r];
        }
    }
    __syncthreads();

    float* qw = sq + w * 256;
    const float* krow = ssum + lane * PITCH;

    for (int e = w; e < cnt; e += 8) {
        const int ent = g_ent[off + e];
        const int h   = ent >> 16;
        const int nv  = ent & 0xffff;
        const size_t qrow = ((size_t)(b * H_ + h)) * NV_ + nv;

        *(float4*)&qw[lane * 8]     = *(const float4*)&g_Qt[qrow * C_ + lane * 8];
        *(float4*)&qw[lane * 8 + 4] = *(const float4*)&g_Qt[qrow * C_ + lane * 8 + 4];
        __syncwarp();

        unsigned long long a0 = 0, a1 = 0, a2 = 0, a3 = 0;
#pragma unroll 8
        for (int c = 0; c < 256; c += 8) {
            const ulonglong2 q01 = *(const ulonglong2*)&qw[c];
            const ulonglong2 q23 = *(const ulonglong2*)&qw[c + 4];
            const ulonglong2 k01 = *(const ulonglong2*)&krow[c];
            const ulonglong2 k23 = *(const ulonglong2*)&krow[c + 4];
            a0 = fma2(q01.x, k01.x, a0);
            a1 = fma2(q01.y, k01.y, a1);
            a2 = fma2(q23.x, k23.x, a2);
            a3 = fma2(q23.y, k23.y, a3);
        }
        const float2 f0 = upk(a0), f1 = upk(a1), f2 = upk(a2), f3 = upk(a3);
        float sc = ((f0.x + f0.y) + (f1.x + f1.y)) + ((f2.x + f2.y) + (f3.x + f3.y));
        sc *= 0.125f;

        float mx = sc;
#pragma unroll
        for (int o = 16; o; o >>= 1) mx = fmaxf(mx, __shfl_xor_sync(0xffffffffu, mx, o));
        const float ex = __expf(sc - mx);
        float sum = ex;
#pragma unroll
        for (int o = 16; o; o >>= 1) sum += __shfl_xor_sync(0xffffffffu, sum, o);
        const float pr = ex / sum;

        unsigned long long b0 = 0, b1 = 0, b2 = 0, b3 = 0;
#pragma unroll 8
        for (int s = 0; s < 32; s++) {
            const float ps = __shfl_sync(0xffffffffu, pr, s);
            unsigned long long pp;
            asm("mov.b64 %0, {%1,%1};" : "=l"(pp) : "r"(__float_as_uint(ps)));
            const ulonglong2 ga = *(const ulonglong2*)&sgf[s * PITCH + lane * 4];
            const ulonglong2 gb = *(const ulonglong2*)&sgf[s * PITCH + 128 + lane * 4];
            b0 = fma2(pp, ga.x, b0);
            b1 = fma2(pp, ga.y, b1);
            b2 = fma2(pp, gb.x, b2);
            b3 = fma2(pp, gb.y, b3);
        }

        const size_t obase = (((size_t)(b * NV_ + nv)) * H_ + h) * C_;
        const float2 g0 = upk(b0), g1 = upk(b1), g2 = upk(b2), g3 = upk(b3);
        __nv_bfloat162 h01, l01, h23, l23;
        split1(g0.x, h01.x, l01.x); split1(g0.y, h01.y, l01.y);
        split1(g1.x, h23.x, l23.x); split1(g1.y, h23.y, l23.y);
        uint2 uh, ul;
        uh.x = *(const unsigned*)&h01; uh.y = *(const unsigned*)&h23;
        ul.x = *(const unsigned*)&l01; ul.y = *(const unsigned*)&l23;
        *(uint2*)&g_Hth[obase + lane * 4] = uh;
        *(uint2*)&g_Htl[obase + lane * 4] = ul;
        split1(g2.x, h01.x, l01.x); split1(g2.y, h01.y, l01.y);
        split1(g3.x, h23.x, l23.x); split1(g3.y, h23.y, l23.y);
        uh.x = *(const unsigned*)&h01; uh.y = *(const unsigned*)&h23;
        ul.x = *(const unsigned*)&l01; ul.y = *(const unsigned*)&l23;
        *(uint2*)&g_Hth[obase + 128 + lane * 4] = uh;
        *(uint2*)&g_Htl[obase + 128 + lane * 4] = ul;
    }
}

// ---------------------------------------------------------------------------
// Launch
// ---------------------------------------------------------------------------
extern "C" void kernel_launch(void* const* d_in, const int* in_sizes, int n_in,
                              void* d_out, int out_size)
{
    const float* q_feat     = (const float*)d_in[0];
    const float* group_feat = (const float*)d_in[1];
    const float* k_pos      = (const float*)d_in[2];
    const int*   nidx       = (const int*)  d_in[3];
    const float* Wq = (const float*)d_in[4];  const float* bq = (const float*)d_in[5];
    const float* Wk = (const float*)d_in[6];
    const float* Wv = (const float*)d_in[8];  const float* bv = (const float*)d_in[9];
    const float* Wo = (const float*)d_in[10]; const float* bo = (const float*)d_in[11];
    float* out = (float*)d_out;

    __nv_bfloat16 *qfh, *qfl, *Qh, *Ql, *Hth, *Htl, *vh, *vl;
    __nv_bfloat16 *Wqh, *Wql, *WkTh, *WkTl, *Wvh, *Wvl, *Woh, *Wol;
    float *Qt, *btld;
    cudaGetSymbolAddress((void**)&qfh, g_qfh);   cudaGetSymbolAddress((void**)&qfl, g_qfl);
    cudaGetSymbolAddress((void**)&Qh,  g_Qh);    cudaGetSymbolAddress((void**)&Ql,  g_Ql);
    cudaGetSymbolAddress((void**)&Hth, g_Hth);   cudaGetSymbolAddress((void**)&Htl, g_Htl);
    cudaGetSymbolAddress((void**)&vh,  g_vh);    cudaGetSymbolAddress((void**)&vl,  g_vl);
    cudaGetSymbolAddress((void**)&Wqh, g_Wqh);   cudaGetSymbolAddress((void**)&Wql, g_Wql);
    cudaGetSymbolAddress((void**)&WkTh, g_WkTh); cudaGetSymbolAddress((void**)&WkTl, g_WkTl);
    cudaGetSymbolAddress((void**)&Wvh, g_Wvh);   cudaGetSymbolAddress((void**)&Wvl, g_Wvl);
    cudaGetSymbolAddress((void**)&Woh, g_Woh);   cudaGetSymbolAddress((void**)&Wol, g_Wol);
    cudaGetSymbolAddress((void**)&Qt,  g_Qt);
    cudaGetSymbolAddress((void**)&btld, g_btld);

    const int attn_smem = (64 * PITCH + 8 * 256) * (int)sizeof(float);  // 74752
    cudaFuncSetAttribute(attn_pages, cudaFuncAttributeMaxDynamicSharedMemorySize,
                         attn_smem);

    // precompute + bucketing
    split_weights<<<256, 256>>>(Wq, Wk, Wv, Wo);
    split_qfeat<<<(MQ * C_ / 4) / 256, 256>>>(q_feat);
    btld_kernel<<<256, 256>>>(Wo, bv, bo);
    hist_kernel<<<NQT / 256, 256>>>(nidx);
    scan_kernel<<<1, 1024>>>();
    scatter_kernel<<<NQT / 256, 256>>>(nidx);

    // Q projection: q_feat @ Wq^T + bq -> g_Q planes [B,H,NV,64]   (mode 0)
    gemm_planes<4><<<dim3(MQ / 128, 2), 256>>>(
        qfh, qfl, C_, Wqh, Wql, C_, C_, bq, nullptr, Qh, Ql, 0, 0, 0);
    // Q-tilde: g_Q @ WkT_h -> g_Qt fp32 [NQT,256]                  (mode 1, qtsel)
    gemm_planes<4><<<dim3(NQT / 128, 2), 256>>>(
        Qh, Ql, DH_, WkTh, WkTl, C_, DH_, nullptr, Qt, nullptr, nullptr, C_, 1, 1);
    // bucketed attention -> g_Hat planes [B,NV,H,256]
    attn_pages<<<NBIN, 256, attn_smem>>>(group_feat, k_pos);
    // vhat: per-head ghat_h @ Wv_h^T -> v planes [MQ,256]          (mode 2)
    gemm_planes<2><<<dim3(MQ / 128, 1, H_), 256>>>(
        Hth, Htl, H_ * C_, Wvh, Wvl, C_, C_, nullptr, nullptr, vh, vl, C_, 2, 0);
    // out: v @ Wo^T + btld -> d_out fp32                            (mode 1)
    gemm_planes<4><<<dim3(MQ / 128, 2), 256>>>(
        vh, vl, C_, Woh, Wol, C_, C_, btld, out, nullptr, nullptr, C_, 1, 0);
}

// round 7
// speedup vs baseline: 1.3169x; 1.1366x over previous
#include <cuda_runtime.h>
#include <cuda_bf16.h>
#include <cstdint>

// ---------------------------------------------------------------------------
// B=2, NV=8192, C=256, NP=2048, NS=32, H=4, DH=64
// ---------------------------------------------------------------------------
namespace {
constexpr int B_   = 2;
constexpr int NV_  = 8192;
constexpr int C_   = 256;
constexpr int NP2  = 2048;
constexpr int NS_  = 32;
constexpr int H_   = 4;
constexpr int DH_  = 64;
constexpr int MQ   = B_ * NV_;          // 16384
constexpr int NQT  = B_ * H_ * NV_;     // 65536 queries
constexpr int NBIN = B_ * NP2;          // 4096 bins
constexpr int SP   = 24;                // gemm smem tile pitch (bf16)
constexpr int PITCH = 260;              // attention page pitch (floats)
}

// operand planes + scratch
__device__ __nv_bfloat16 g_qfh[(size_t)MQ * C_],  g_qfl[(size_t)MQ * C_];
__device__ __nv_bfloat16 g_Qh [(size_t)NQT * DH_], g_Ql [(size_t)NQT * DH_];
__device__ float         g_Qt [(size_t)NQT * C_];                    // fp32, 64MB
__device__ __nv_bfloat16 g_Hth[(size_t)MQ * H_ * C_], g_Htl[(size_t)MQ * H_ * C_];
__device__ __nv_bfloat16 g_vh [(size_t)MQ * C_],  g_vl [(size_t)MQ * C_];
__device__ __nv_bfloat16 g_Wqh[C_ * C_], g_Wql[C_ * C_];
__device__ __nv_bfloat16 g_WkTh[C_ * C_], g_WkTl[C_ * C_];
__device__ __nv_bfloat16 g_Wvh[C_ * C_], g_Wvl[C_ * C_];
__device__ __nv_bfloat16 g_Woh[C_ * C_], g_Wol[C_ * C_];
__device__ float g_btld[C_];
__device__ int   g_cnt[NBIN];            // zero-init at load; scan re-zeroes
__device__ int   g_off[NBIN + 1];
__device__ int   g_cur[NBIN];
__device__ int   g_ent[NQT];

// ---------------------------------------------------------------------------
// helpers
// ---------------------------------------------------------------------------
__device__ __forceinline__ uint32_t smem_u32(const void* p) {
    return (uint32_t)__cvta_generic_to_shared(p);
}
__device__ __forceinline__ void ldsm4(uint32_t r[4], uint32_t a) {
    asm volatile("ldmatrix.sync.aligned.m8n8.x4.shared.b16 {%0,%1,%2,%3}, [%4];\n"
                 : "=r"(r[0]), "=r"(r[1]), "=r"(r[2]), "=r"(r[3]) : "r"(a));
}
__device__ __forceinline__ void mma_bf16(float c[4], const uint32_t a[4], const uint32_t b[2]) {
    asm volatile(
        "mma.sync.aligned.m16n8k16.row.col.f32.bf16.bf16.f32 "
        "{%0,%1,%2,%3}, {%4,%5,%6,%7}, {%8,%9}, {%0,%1,%2,%3};\n"
        : "+f"(c[0]), "+f"(c[1]), "+f"(c[2]), "+f"(c[3])
        : "r"(a[0]), "r"(a[1]), "r"(a[2]), "r"(a[3]), "r"(b[0]), "r"(b[1]));
}
__device__ __forceinline__ void split1(float x, __nv_bfloat16& h, __nv_bfloat16& l) {
    h = __float2bfloat16(x);
    l = __float2bfloat16(x - __bfloat162float(h));
}
__device__ __forceinline__ unsigned long long fma2(unsigned long long a,
                                                   unsigned long long b,
                                                   unsigned long long c) {
    unsigned long long d;
    asm("fma.rn.f32x2 %0, %1, %2, %3;" : "=l"(d) : "l"(a), "l"(b), "l"(c));
    return d;
}
__device__ __forceinline__ float2 upk(unsigned long long v) {
    return make_float2(__uint_as_float((unsigned)v),
                       __uint_as_float((unsigned)(v >> 32)));
}

// ---------------------------------------------------------------------------
// GEMM on pre-split bf16 planes (3-term bf16x3 emulation of fp32).
// ---------------------------------------------------------------------------
template <int NFRAG>
__global__ void __launch_bounds__(256, 1)
gemm_planes(const __nv_bfloat16* __restrict__ Ah, const __nv_bfloat16* __restrict__ Al,
            int lda,
            const __nv_bfloat16* __restrict__ Bh, const __nv_bfloat16* __restrict__ Bl,
            int ldb, int K,
            const float* __restrict__ bias,
            float* __restrict__ outf,
            __nv_bfloat16* __restrict__ oph, __nv_bfloat16* __restrict__ opl,
            int ldo, int mode, int qtsel)
{
    constexpr int NT = 32 * NFRAG;
    __shared__ __align__(16) __nv_bfloat16 sAh[2][128][SP];
    __shared__ __align__(16) __nv_bfloat16 sAl[2][128][SP];
    __shared__ __align__(16) __nv_bfloat16 sBh[2][NT][SP];
    __shared__ __align__(16) __nv_bfloat16 sBl[2][NT][SP];

    const int m0   = blockIdx.x * 128;
    const int n0   = blockIdx.y * NT;
    const int tid  = threadIdx.x;
    const int lane = tid & 31;
    const int wid  = tid >> 5;
    const int wm   = (wid & 1) * 64;
    const int wn   = (wid >> 1) * (8 * NFRAG);

    const int koff = qtsel ? ((m0 >> 13) & 3) * 64 : 0;
    const __nv_bfloat16* Ahp = Ah;
    const __nv_bfloat16* Alp = Al;
    const __nv_bfloat16* Bhp = Bh;
    const __nv_bfloat16* Blp = Bl;
    int ncol_off = 0;
    if (mode == 2) {
        const int hz = blockIdx.z;
        Ahp += hz * 256;  Alp += hz * 256;
        Bhp += (size_t)hz * 64 * ldb;  Blp += (size_t)hz * 64 * ldb;
        ncol_off = hz * 64;
    }

    const int am = tid >> 1;
    const int ak = (tid & 1) << 3;
    const int bn = tid >> 1;
    const int bk = (tid & 1) << 3;
    const bool bact = (NFRAG == 4) || (tid < 2 * NT);

    const int lrow = (lane & 7) + (lane & 8);
    const int lcol = (lane & 16) ? 8 : 0;
    const int fn = lane >> 2;
    const int fc = (lane & 3) * 2;

    float acc[4][NFRAG][4];
#pragma unroll
    for (int i = 0; i < 4; i++)
#pragma unroll
        for (int j = 0; j < NFRAG; j++)
#pragma unroll
            for (int r = 0; r < 4; r++) acc[i][j][r] = 0.f;

    uint4 rah, ral, rbh, rbl;
    auto ldg_chunk = [&](int kc) {
        const int k0 = kc * 16;
        rah = *(const uint4*)&Ahp[(size_t)(m0 + am) * lda + k0 + ak];
        ral = *(const uint4*)&Alp[(size_t)(m0 + am) * lda + k0 + ak];
        if (bact) {
            rbh = *(const uint4*)&Bhp[(size_t)(n0 + bn) * ldb + koff + k0 + bk];
            rbl = *(const uint4*)&Blp[(size_t)(n0 + bn) * ldb + koff + k0 + bk];
        }
    };
    auto st_chunk = [&](int buf) {
        *(uint4*)&sAh[buf][am][ak] = rah;
        *(uint4*)&sAl[buf][am][ak] = ral;
        if (bact) {
            *(uint4*)&sBh[buf][bn][bk] = rbh;
            *(uint4*)&sBl[buf][bn][bk] = rbl;
        }
    };
    auto compute = [&](int buf) {
        uint32_t Ahf[4][4], Alf[4][4], Bhf[NFRAG][2], Blf[NFRAG][2];
#pragma unroll
        for (int mf = 0; mf < 4; mf++) {
            const int mr = wm + mf * 16 + lrow;
            ldsm4(Ahf[mf], smem_u32(&sAh[buf][mr][lcol]));
            ldsm4(Alf[mf], smem_u32(&sAl[buf][mr][lcol]));
        }
#pragma unroll
        for (int nf = 0; nf < NFRAG; nf++) {
            const int n = wn + nf * 8 + fn;
            Bhf[nf][0] = *(const uint32_t*)&sBh[buf][n][fc];
            Bhf[nf][1] = *(const uint32_t*)&sBh[buf][n][fc + 8];
            Blf[nf][0] = *(const uint32_t*)&sBl[buf][n][fc];
            Blf[nf][1] = *(const uint32_t*)&sBl[buf][n][fc + 8];
        }
#pragma unroll
        for (int mf = 0; mf < 4; mf++)
#pragma unroll
            for (int nf = 0; nf < NFRAG; nf++) {
                mma_bf16(acc[mf][nf], Ahf[mf], Bhf[nf]);
                mma_bf16(acc[mf][nf], Ahf[mf], Blf[nf]);
                mma_bf16(acc[mf][nf], Alf[mf], Bhf[nf]);
            }
    };

    const int NKC = K / 16;
    ldg_chunk(0);
    st_chunk(0);
    __syncthreads();
    for (int kc = 0; kc < NKC; kc++) {
        const int buf = kc & 1;
        if (kc + 1 < NKC) ldg_chunk(kc + 1);
        compute(buf);
        if (kc + 1 < NKC) {
            st_chunk(buf ^ 1);
            __syncthreads();
        }
    }

#pragma unroll
    for (int mf = 0; mf < 4; mf++)
#pragma unroll
        for (int nf = 0; nf < NFRAG; nf++) {
            const int ncol = n0 + wn + nf * 8 + fc;
            const float bx = bias ? bias[ncol]     : 0.f;
            const float by = bias ? bias[ncol + 1] : 0.f;
#pragma unroll
            for (int half = 0; half < 2; half++) {
                const int mrow = m0 + wm + mf * 16 + (lane >> 2) + half * 8;
                const float ox = acc[mf][nf][half * 2]     + bx;
                const float oy = acc[mf][nf][half * 2 + 1] + by;
                if (mode == 0) {
                    const int bb = mrow >> 13;
                    const int nv = mrow & (NV_ - 1);
                    const int hh = ncol >> 6;
                    const int d  = ncol & 63;
                    const size_t idx = (((size_t)(bb * H_ + hh)) * NV_ + nv) * DH_ + d;
                    __nv_bfloat162 h2, l2;
                    split1(ox, h2.x, l2.x);
                    split1(oy, h2.y, l2.y);
                    *(__nv_bfloat162*)&oph[idx] = h2;
                    *(__nv_bfloat162*)&opl[idx] = l2;
                } else if (mode == 1) {
                    float2 o; o.x = ox; o.y = oy;
                    *(float2*)&outf[(size_t)mrow * ldo + ncol] = o;
                } else {
                    const size_t idx = (size_t)mrow * ldo + ncol_off + ncol;
                    __nv_bfloat162 h2, l2;
                    split1(ox, h2.x, l2.x);
                    split1(oy, h2.y, l2.y);
                    *(__nv_bfloat162*)&oph[idx] = h2;
                    *(__nv_bfloat162*)&opl[idx] = l2;
                }
            }
        }
}

// ---------------------------------------------------------------------------
// Merged prep: [0,256) weight split, [256,512) btld, [512,4608) qfeat split,
// [4608,4864) histogram. All branches independent.
// ---------------------------------------------------------------------------
__global__ void prep_kernel(const float* __restrict__ Wq,
                            const float* __restrict__ Wk,
                            const float* __restrict__ Wv,
                            const float* __restrict__ Wo,
                            const float* __restrict__ bv,
                            const float* __restrict__ bo,
                            const float* __restrict__ qf,
                            const int*   __restrict__ nidx)
{
    const int bid = blockIdx.x;
    const int t   = threadIdx.x;
    if (bid < 256) {
        const int i = bid * C_ + t;
        split1(Wq[i], g_Wqh[i], g_Wql[i]);
        split1(Wk[t * C_ + bid], g_WkTh[i], g_WkTl[i]);
        split1(Wv[i], g_Wvh[i], g_Wvl[i]);
        split1(Wo[i], g_Woh[i], g_Wol[i]);
    } else if (bid < 512) {
        __shared__ float red[256];
        const int i = bid - 256;
        red[t] = Wo[(size_t)i * C_ + t] * bv[t];
        __syncthreads();
#pragma unroll
        for (int o = 128; o; o >>= 1) {
            if (t < o) red[t] += red[t + o];
            __syncthreads();
        }
        if (t == 0) g_btld[i] = red[0] + bo[i];
    } else if (bid < 4608) {
        const int idx = (bid - 512) * 256 + t;        // 1M float4
        const float4 v = ((const float4*)qf)[idx];
        __nv_bfloat16 h[4], l[4];
        split1(v.x, h[0], l[0]); split1(v.y, h[1], l[1]);
        split1(v.z, h[2], l[2]); split1(v.w, h[3], l[3]);
        *(uint2*)&g_qfh[(size_t)idx * 4] = *(const uint2*)h;
        *(uint2*)&g_qfl[(size_t)idx * 4] = *(const uint2*)l;
    } else {
        const int q = (bid - 4608) * 256 + t;         // 65536
        const int b = q >> 15;
        atomicAdd(&g_cnt[(b << 11) | nidx[q]], 1);
    }
}

// scan + re-zero g_cnt (so next graph replay starts clean)
__global__ void scan_kernel() {
    __shared__ int tsum[1024];
    const int t = threadIdx.x;
    const int4 v = ((const int4*)g_cnt)[t];
    ((int4*)g_cnt)[t] = make_int4(0, 0, 0, 0);
    const int s0 = v.x, s01 = v.x + v.y, s012 = s01 + v.z;
    const int tot = s012 + v.w;
    tsum[t] = tot;
    __syncthreads();
    for (int off = 1; off < 1024; off <<= 1) {
        int x = (t >= off) ? tsum[t - off] : 0;
        __syncthreads();
        tsum[t] += x;
        __syncthreads();
    }
    const int base = tsum[t] - tot;
    g_off[4 * t]     = base;          g_cur[4 * t]     = base;
    g_off[4 * t + 1] = base + s0;     g_cur[4 * t + 1] = base + s0;
    g_off[4 * t + 2] = base + s01;    g_cur[4 * t + 2] = base + s01;
    g_off[4 * t + 3] = base + s012;   g_cur[4 * t + 3] = base + s012;
    if (t == 1023) g_off[NBIN] = tsum[1023];
}

__global__ void scatter_kernel(const int* __restrict__ nidx) {
    const int t = blockIdx.x * 256 + threadIdx.x;
    const int b  = t >> 15;
    const int h  = (t >> 13) & 3;
    const int nv = t & (NV_ - 1);
    const int pos = atomicAdd(&g_cur[(b << 11) | nidx[t]], 1);
    g_ent[pos] = (h << 16) | nv;
}

// ---------------------------------------------------------------------------
// Bucketed attention: s-major pages, f32x2 math, 2 queries per warp pass.
// smem: ssum[32][PITCH], sgf[32][PITCH], sq[8][512]
// ---------------------------------------------------------------------------
__global__ void __launch_bounds__(256)
attn_pages(const float* __restrict__ gf, const float* __restrict__ kp)
{
    extern __shared__ float sm[];
    float* ssum = sm;
    float* sgf  = sm + 32 * PITCH;
    float* sq   = sm + 64 * PITCH;

    const int bin  = blockIdx.x;
    const int b    = bin >> 11;
    const int page = bin & (NP2 - 1);
    const int off  = g_off[bin];
    const int cnt  = g_off[bin + 1] - off;
    if (cnt == 0) return;

    const int tid  = threadIdx.x;
    const int lane = tid & 31;
    const int w    = tid >> 5;

    const float* gfb = gf + (size_t)b * C_ * (NP2 * NS_) + page * NS_;
    const float* kpb = kp + (size_t)b * C_ * (NP2 * NS_) + page * NS_;

#pragma unroll
    for (int it = 0; it < 8; it++) {
        const int i = it * 256 + tid;
        const int c = i >> 3;
        const int j = (i & 7) * 4;
        const float4 g = *(const float4*)(gfb + (size_t)c * (NP2 * NS_) + j);
        const float4 k = *(const float4*)(kpb + (size_t)c * (NP2 * NS_) + j);
        const float gr[4] = {g.x, g.y, g.z, g.w};
        const float kr[4] = {k.x, k.y, k.z, k.w};
#pragma unroll
        for (int r = 0; r < 4; r++) {
            sgf [(j + r) * PITCH + c] = gr[r];
            ssum[(j + r) * PITCH + c] = gr[r] + kr[r];
        }
    }
    __syncthreads();

    float* qw = sq + w * 512;
    const float* krow = ssum + lane * PITCH;

    for (int e = 2 * w; e < cnt; e += 16) {
        const int  e1v   = (e + 1 < cnt) ? e + 1 : e;
        const int  ent0  = g_ent[off + e];
        const int  ent1  = g_ent[off + e1v];
        const int  h0 = ent0 >> 16, nv0 = ent0 & 0xffff;
        const int  h1 = ent1 >> 16, nv1 = ent1 & 0xffff;
        const size_t qr0 = ((size_t)(b * H_ + h0)) * NV_ + nv0;
        const size_t qr1 = ((size_t)(b * H_ + h1)) * NV_ + nv1;

        // stage both query rows
        *(float4*)&qw[lane * 8]           = *(const float4*)&g_Qt[qr0 * C_ + lane * 8];
        *(float4*)&qw[lane * 8 + 4]       = *(const float4*)&g_Qt[qr0 * C_ + lane * 8 + 4];
        *(float4*)&qw[512 - 256 + lane * 8]     = *(const float4*)&g_Qt[qr1 * C_ + lane * 8];
        *(float4*)&qw[512 - 256 + lane * 8 + 4] = *(const float4*)&g_Qt[qr1 * C_ + lane * 8 + 4];
        __syncwarp();

        // scores for s = lane, both queries; shared K-row loads
        unsigned long long a00 = 0, a01 = 0, a02 = 0, a03 = 0;
        unsigned long long a10 = 0, a11 = 0, a12 = 0, a13 = 0;
#pragma unroll 8
        for (int c = 0; c < 256; c += 8) {
            const ulonglong2 k01 = *(const ulonglong2*)&krow[c];
            const ulonglong2 k23 = *(const ulonglong2*)&krow[c + 4];
            const ulonglong2 p01 = *(const ulonglong2*)&qw[c];
            const ulonglong2 p23 = *(const ulonglong2*)&qw[c + 4];
            const ulonglong2 r01 = *(const ulonglong2*)&qw[256 + c];
            const ulonglong2 r23 = *(const ulonglong2*)&qw[256 + c + 4];
            a00 = fma2(p01.x, k01.x, a00);
            a01 = fma2(p01.y, k01.y, a01);
            a02 = fma2(p23.x, k23.x, a02);
            a03 = fma2(p23.y, k23.y, a03);
            a10 = fma2(r01.x, k01.x, a10);
            a11 = fma2(r01.y, k01.y, a11);
            a12 = fma2(r23.x, k23.x, a12);
            a13 = fma2(r23.y, k23.y, a13);
        }
        const float2 f00 = upk(a00), f01 = upk(a01), f02 = upk(a02), f03 = upk(a03);
        const float2 f10 = upk(a10), f11 = upk(a11), f12 = upk(a12), f13 = upk(a13);
        float sc0 = ((f00.x + f00.y) + (f01.x + f01.y)) + ((f02.x + f02.y) + (f03.x + f03.y));
        float sc1 = ((f10.x + f10.y) + (f11.x + f11.y)) + ((f12.x + f12.y) + (f13.x + f13.y));
        sc0 *= 0.125f;
        sc1 *= 0.125f;

        // softmax over 32 lanes, both queries interleaved
        float mx0 = sc0, mx1 = sc1;
#pragma unroll
        for (int o = 16; o; o >>= 1) {
            mx0 = fmaxf(mx0, __shfl_xor_sync(0xffffffffu, mx0, o));
            mx1 = fmaxf(mx1, __shfl_xor_sync(0xffffffffu, mx1, o));
        }
        const float ex0 = __expf(sc0 - mx0);
        const float ex1 = __expf(sc1 - mx1);
        float su0 = ex0, su1 = ex1;
#pragma unroll
        for (int o = 16; o; o >>= 1) {
            su0 += __shfl_xor_sync(0xffffffffu, su0, o);
            su1 += __shfl_xor_sync(0xffffffffu, su1, o);
        }
        const float pr0 = ex0 / su0;
        const float pr1 = ex1 / su1;

        // ghat, shared gf-row loads
        unsigned long long b00 = 0, b01 = 0, b02 = 0, b03 = 0;
        unsigned long long b10 = 0, b11 = 0, b12 = 0, b13 = 0;
#pragma unroll 8
        for (int s = 0; s < 32; s++) {
            const float ps0 = __shfl_sync(0xffffffffu, pr0, s);
            const float ps1 = __shfl_sync(0xffffffffu, pr1, s);
            unsigned long long pp0, pp1;
            asm("mov.b64 %0, {%1,%1};" : "=l"(pp0) : "r"(__float_as_uint(ps0)));
            asm("mov.b64 %0, {%1,%1};" : "=l"(pp1) : "r"(__float_as_uint(ps1)));
            const ulonglong2 ga = *(const ulonglong2*)&sgf[s * PITCH + lane * 4];
            const ulonglong2 gb = *(const ulonglong2*)&sgf[s * PITCH + 128 + lane * 4];
            b00 = fma2(pp0, ga.x, b00);
            b01 = fma2(pp0, ga.y, b01);
            b02 = fma2(pp0, gb.x, b02);
            b03 = fma2(pp0, gb.y, b03);
            b10 = fma2(pp1, ga.x, b10);
            b11 = fma2(pp1, ga.y, b11);
            b12 = fma2(pp1, gb.x, b12);
            b13 = fma2(pp1, gb.y, b13);
        }

        auto write_hat = [&](int bq, int hq, int nvq,
                             unsigned long long c0, unsigned long long c1,
                             unsigned long long c2, unsigned long long c3) {
            const size_t obase = (((size_t)(bq * NV_ + nvq)) * H_ + hq) * C_;
            const float2 g0 = upk(c0), g1 = upk(c1), g2 = upk(c2), g3 = upk(c3);
            __nv_bfloat162 h01, l01, h23, l23;
            uint2 uh, ul;
            split1(g0.x, h01.x, l01.x); split1(g0.y, h01.y, l01.y);
            split1(g1.x, h23.x, l23.x); split1(g1.y, h23.y, l23.y);
            uh.x = *(const unsigned*)&h01; uh.y = *(const unsigned*)&h23;
            ul.x = *(const unsigned*)&l01; ul.y = *(const unsigned*)&l23;
            *(uint2*)&g_Hth[obase + lane * 4] = uh;
            *(uint2*)&g_Htl[obase + lane * 4] = ul;
            split1(g2.x, h01.x, l01.x); split1(g2.y, h01.y, l01.y);
            split1(g3.x, h23.x, l23.x); split1(g3.y, h23.y, l23.y);
            uh.x = *(const unsigned*)&h01; uh.y = *(const unsigned*)&h23;
            ul.x = *(const unsigned*)&l01; ul.y = *(const unsigned*)&l23;
            *(uint2*)&g_Hth[obase + 128 + lane * 4] = uh;
            *(uint2*)&g_Htl[obase + 128 + lane * 4] = ul;
        };
        write_hat(b, h0, nv0, b00, b01, b02, b03);
        if (e + 1 < cnt) write_hat(b, h1, nv1, b10, b11, b12, b13);
    }
}

// ---------------------------------------------------------------------------
// Launch
// ---------------------------------------------------------------------------
extern "C" void kernel_launch(void* const* d_in, const int* in_sizes, int n_in,
                              void* d_out, int out_size)
{
    const float* q_feat     = (const float*)d_in[0];
    const float* group_feat = (const float*)d_in[1];
    const float* k_pos      = (const float*)d_in[2];
    const int*   nidx       = (const int*)  d_in[3];
    const float* Wq = (const float*)d_in[4];  const float* bq = (const float*)d_in[5];
    const float* Wk = (const float*)d_in[6];
    const float* Wv = (const float*)d_in[8];  const float* bv = (const float*)d_in[9];
    const float* Wo = (const float*)d_in[10]; const float* bo = (const float*)d_in[11];
    float* out = (float*)d_out;

    __nv_bfloat16 *qfh, *qfl, *Qh, *Ql, *Hth, *Htl, *vh, *vl;
    __nv_bfloat16 *Wqh, *Wql, *WkTh, *WkTl, *Wvh, *Wvl, *Woh, *Wol;
    float *Qt, *btld;
    cudaGetSymbolAddress((void**)&qfh, g_qfh);   cudaGetSymbolAddress((void**)&qfl, g_qfl);
    cudaGetSymbolAddress((void**)&Qh,  g_Qh);    cudaGetSymbolAddress((void**)&Ql,  g_Ql);
    cudaGetSymbolAddress((void**)&Hth, g_Hth);   cudaGetSymbolAddress((void**)&Htl, g_Htl);
    cudaGetSymbolAddress((void**)&vh,  g_vh);    cudaGetSymbolAddress((void**)&vl,  g_vl);
    cudaGetSymbolAddress((void**)&Wqh, g_Wqh);   cudaGetSymbolAddress((void**)&Wql, g_Wql);
    cudaGetSymbolAddress((void**)&WkTh, g_WkTh); cudaGetSymbolAddress((void**)&WkTl, g_WkTl);
    cudaGetSymbolAddress((void**)&Wvh, g_Wvh);   cudaGetSymbolAddress((void**)&Wvl, g_Wvl);
    cudaGetSymbolAddress((void**)&Woh, g_Woh);   cudaGetSymbolAddress((void**)&Wol, g_Wol);
    cudaGetSymbolAddress((void**)&Qt,  g_Qt);
    cudaGetSymbolAddress((void**)&btld, g_btld);

    const int attn_smem = (64 * PITCH + 8 * 512) * (int)sizeof(float);  // 82944
    cudaFuncSetAttribute(attn_pages, cudaFuncAttributeMaxDynamicSharedMemorySize,
                         attn_smem);

    // merged prep (weights, btld, qfeat split, histogram) + scan + scatter
    prep_kernel<<<4864, 256>>>(Wq, Wk, Wv, Wo, bv, bo, q_feat, nidx);
    scan_kernel<<<1, 1024>>>();
    scatter_kernel<<<NQT / 256, 256>>>(nidx);

    // Q projection: q_feat @ Wq^T + bq -> g_Q planes [B,H,NV,64]   (mode 0)
    gemm_planes<4><<<dim3(MQ / 128, 2), 256>>>(
        qfh, qfl, C_, Wqh, Wql, C_, C_, bq, nullptr, Qh, Ql, 0, 0, 0);
    // Q-tilde: g_Q @ WkT_h -> g_Qt fp32 [NQT,256]                  (mode 1, qtsel)
    gemm_planes<4><<<dim3(NQT / 128, 2), 256>>>(
        Qh, Ql, DH_, WkTh, WkTl, C_, DH_, nullptr, Qt, nullptr, nullptr, C_, 1, 1);
    // bucketed attention -> g_Hat planes [B,NV,H,256]
    attn_pages<<<NBIN, 256, attn_smem>>>(group_feat, k_pos);
    // vhat: per-head ghat_h @ Wv_h^T -> v planes [MQ,256]          (mode 2)
    gemm_planes<2><<<dim3(MQ / 128, 1, H_), 256>>>(
        Hth, Htl, H_ * C_, Wvh, Wvl, C_, C_, nullptr, nullptr, vh, vl, C_, 2, 0);
    // out: v @ Wo^T + btld -> d_out fp32                            (mode 1)
    gemm_planes<4><<<dim3(MQ / 128, 2), 256>>>(
        vh, vl, C_, Woh, Wol, C_, C_, btld, out, nullptr, nullptr, C_, 1, 0);
}